// round 3
// baseline (speedup 1.0000x reference)
#include <cuda_runtime.h>
#include <math.h>

// Problem constants
#define NBATCH   64
#define NCH      128
#define NPTS     256           // 16x16 image grid
#define MAPS     32            // BEV map size
#define NCELLS   (MAPS*MAPS)   // 1024
#define HMAXV    14
#define GROUPS   16            // channel groups per batch
#define CH_PER   (NCH / GROUPS)   // 8

__global__ __launch_bounds__(256)
void voxelize_kernel(const float* __restrict__ features,   // (64,128,256)
                     const float* __restrict__ depth,      // (64,1,256)
                     const float* __restrict__ cam,        // (3,256)
                     float* __restrict__ out)              // (64,128,32,32)
{
    __shared__ __align__(16) int besty[NCELLS];   // highest occupied y per cell
    __shared__ __align__(16) int head [NCELLS];   // linked-list head of winning points
    __shared__ int nxt[NPTS];

    const int tid = threadIdx.x;        // 0..255 == point id
    const int b   = blockIdx.y;         // batch
    const int g   = blockIdx.x;         // channel group
    const int cl4 = tid * 4;            // this thread's 4 cells

    // init shared (vectorized: each thread owns 4 cells)
    const int4 neg4 = make_int4(-1, -1, -1, -1);
    *reinterpret_cast<int4*>(&besty[cl4]) = neg4;
    *reinterpret_cast<int4*>(&head [cl4]) = neg4;

    // ---- per-point voxel index math (bit-exact vs JAX float32) ----
    const float d  = depth[b * NPTS + tid];
    const float cx = cam[          tid];
    const float cy = cam[  NPTS  + tid];
    const float cz = cam[2*NPTS  + tid];

    const float px = __fmul_rn(d, cx);
    const float py = __fadd_rn(__fmul_rn(d, cy), 1.72f);   // + CAM_HEIGHT
    const float pz = __fmul_rn(d, cz);

    const float CELLF = 0.1f;  // float32(3.2/32)
    const int xi = (int)floorf(__fdiv_rn(px, CELLF)) + (MAPS / 2);
    const int yi = (int)floorf(__fdiv_rn(py, CELLF));
    const int zi = (int)floorf(__fdiv_rn(pz, CELLF)) + MAPS;

    const bool valid = (xi >= 0) & (xi < MAPS) & (zi >= 0) & (zi < MAPS) & (yi < HMAXV);

    // replicate reference flat index semantics: flat = (z*32+x)*14 + y
    int cell = -1, ye = -1;
    if (valid) {
        const int vflat = (zi * MAPS + xi) * HMAXV + yi;
        if (vflat >= 0) {
            cell = vflat / HMAXV;
            ye   = vflat - cell * HMAXV;
        }
    }
    __syncthreads();

    // ---- phase 1: per-cell highest occupied y ----
    if (cell >= 0) atomicMax(&besty[cell], ye);
    __syncthreads();

    // ---- phase 1.5: linked list of points at the winning voxel ----
    if (cell >= 0 && ye == besty[cell]) {
        nxt[tid] = atomicExch(&head[cell], tid);
    }
    __syncthreads();

    // ---- resolve this thread's 4 cells ONCE (channel-invariant) ----
    const int4 h = *reinterpret_cast<const int4*>(&head[cl4]);
    const bool e0 = h.x < 0, e1 = h.y < 0, e2 = h.z < 0, e3 = h.w < 0;
    const bool allEmpty = e0 & e1 & e2 & e3;
    const bool multi = (!e0 && nxt[h.x] >= 0) | (!e1 && nxt[h.y] >= 0)
                     | (!e2 && nxt[h.z] >= 0) | (!e3 && nxt[h.w] >= 0);

    const float* __restrict__ fb = features + (size_t)(b * NCH + g * CH_PER) * NPTS;
    float*       __restrict__ ob = out      + (size_t)(b * NCH + g * CH_PER) * NCELLS + cl4;

    if (allEmpty) {
        // ~68% of threads: pure zero streaming, no loads
        const float4 z = make_float4(0.f, 0.f, 0.f, 0.f);
        #pragma unroll
        for (int c = 0; c < CH_PER; c++)
            *reinterpret_cast<float4*>(ob + c * NCELLS) = z;
    } else if (!multi) {
        // common occupied path: issue ALL gathers (high MLP), then all stores
        float4 v[CH_PER];
        #pragma unroll
        for (int c = 0; c < CH_PER; c++) {
            const float* __restrict__ frow = fb + c * NPTS;
            v[c].x = e0 ? 0.f : frow[h.x];
            v[c].y = e1 ? 0.f : frow[h.y];
            v[c].z = e2 ? 0.f : frow[h.z];
            v[c].w = e3 ? 0.f : frow[h.w];
        }
        #pragma unroll
        for (int c = 0; c < CH_PER; c++)
            *reinterpret_cast<float4*>(ob + c * NCELLS) = v[c];
    } else {
        // rare: some cell has multiple points in its winning voxel -> sum the list
        for (int c = 0; c < CH_PER; c++) {
            const float* __restrict__ frow = fb + c * NPTS;
            float v[4];
            #pragma unroll
            for (int j = 0; j < 4; j++) {
                int q = head[cl4 + j];
                float s = 0.f;
                while (q >= 0) { s += frow[q]; q = nxt[q]; }
                v[j] = s;
            }
            *reinterpret_cast<float4*>(ob + c * NCELLS) =
                make_float4(v[0], v[1], v[2], v[3]);
        }
    }
}

extern "C" void kernel_launch(void* const* d_in, const int* in_sizes, int n_in,
                              void* d_out, int out_size)
{
    const float* features = (const float*)d_in[0];   // 64*128*16*16
    const float* depth    = (const float*)d_in[1];   // 64*1*16*16
    const float* cam      = (const float*)d_in[2];   // 3*256
    float*       out      = (float*)d_out;           // 64*128*32*32

    dim3 grid(GROUPS, NBATCH);
    voxelize_kernel<<<grid, 256>>>(features, depth, cam, out);
}

// round 4
// speedup vs baseline: 1.3075x; 1.3075x over previous
#include <cuda_runtime.h>
#include <math.h>

// Problem constants
#define NBATCH   64
#define NCH      128
#define NPTS     256           // 16x16 image grid
#define MAPS     32            // BEV map size
#define NCELLS   (MAPS*MAPS)   // 1024
#define HMAXV    14
#define GROUPS   16            // channel groups per batch
#define CH_PER   (NCH / GROUPS)   // 8

__global__ __launch_bounds__(256)
void voxelize_kernel(const float* __restrict__ features,   // (64,128,256)
                     const float* __restrict__ depth,      // (64,1,256)
                     const float* __restrict__ cam,        // (3,256)
                     float* __restrict__ out)              // (64,128,32,32)
{
    __shared__ __align__(16) int besty[NCELLS];   // highest occupied y per cell
    __shared__ __align__(16) int head [NCELLS];   // linked-list head of winning points
    __shared__ int nxt[NPTS];
    __shared__ __align__(16) float sf[CH_PER * NPTS];   // staged feature slice (8KB)

    const int tid = threadIdx.x;        // 0..255 == point id
    const int b   = blockIdx.y;         // batch
    const int g   = blockIdx.x;         // channel group
    const int cl4 = tid * 4;            // this thread's 4 cells

    // init shared (vectorized: each thread owns 4 cells)
    const int4 neg4 = make_int4(-1, -1, -1, -1);
    *reinterpret_cast<int4*>(&besty[cl4]) = neg4;
    *reinterpret_cast<int4*>(&head [cl4]) = neg4;

    // ---- stage this block's feature slice into smem (coalesced LDG.128) ----
    const float* __restrict__ fb = features + (size_t)(b * NCH + g * CH_PER) * NPTS;
    {
        const float4* __restrict__ src = reinterpret_cast<const float4*>(fb);
        float4* dst = reinterpret_cast<float4*>(sf);
        #pragma unroll
        for (int i = 0; i < (CH_PER * NPTS / 4) / 256; i++)
            dst[tid + i * 256] = src[tid + i * 256];
    }

    // ---- per-point voxel index math (bit-exact vs JAX float32) ----
    const float d  = depth[b * NPTS + tid];
    const float cx = cam[          tid];
    const float cy = cam[  NPTS  + tid];
    const float cz = cam[2*NPTS  + tid];

    const float px = __fmul_rn(d, cx);
    const float py = __fadd_rn(__fmul_rn(d, cy), 1.72f);   // + CAM_HEIGHT
    const float pz = __fmul_rn(d, cz);

    const float CELLF = 0.1f;  // float32(3.2/32)
    const int xi = (int)floorf(__fdiv_rn(px, CELLF)) + (MAPS / 2);
    const int yi = (int)floorf(__fdiv_rn(py, CELLF));
    const int zi = (int)floorf(__fdiv_rn(pz, CELLF)) + MAPS;

    const bool valid = (xi >= 0) & (xi < MAPS) & (zi >= 0) & (zi < MAPS) & (yi < HMAXV);

    // replicate reference flat index semantics: flat = (z*32+x)*14 + y
    int cell = -1, ye = -1;
    if (valid) {
        const int vflat = (zi * MAPS + xi) * HMAXV + yi;
        if (vflat >= 0) {
            cell = vflat / HMAXV;
            ye   = vflat - cell * HMAXV;
        }
    }
    __syncthreads();

    // ---- phase 1: per-cell highest occupied y ----
    if (cell >= 0) atomicMax(&besty[cell], ye);
    __syncthreads();

    // ---- phase 1.5: linked list of points at the winning voxel ----
    if (cell >= 0 && ye == besty[cell]) {
        nxt[tid] = atomicExch(&head[cell], tid);
    }
    __syncthreads();

    // ---- resolve this thread's 4 cells ONCE (channel-invariant) ----
    const int4 h = *reinterpret_cast<const int4*>(&head[cl4]);
    const bool e0 = h.x < 0, e1 = h.y < 0, e2 = h.z < 0, e3 = h.w < 0;
    // clamp indices so predicated-off lanes still read in-bounds smem
    const int i0 = e0 ? 0 : h.x;
    const int i1 = e1 ? 0 : h.y;
    const int i2 = e2 ? 0 : h.z;
    const int i3 = e3 ? 0 : h.w;
    const bool multi = (!e0 && nxt[i0] >= 0) | (!e1 && nxt[i1] >= 0)
                     | (!e2 && nxt[i2] >= 0) | (!e3 && nxt[i3] >= 0);

    float* __restrict__ ob = out + (size_t)(b * NCH + g * CH_PER) * NCELLS + cl4;

    if (!multi) {
        // common path (incl. empty cells): gather from SMEM, coalesced STG.128
        #pragma unroll
        for (int c = 0; c < CH_PER; c++) {
            const float* __restrict__ frow = sf + c * NPTS;
            float4 v;
            v.x = e0 ? 0.f : frow[i0];
            v.y = e1 ? 0.f : frow[i1];
            v.z = e2 ? 0.f : frow[i2];
            v.w = e3 ? 0.f : frow[i3];
            *reinterpret_cast<float4*>(ob + c * NCELLS) = v;
        }
    } else {
        // rare: some cell has multiple points in its winning voxel -> sum the list
        for (int c = 0; c < CH_PER; c++) {
            const float* __restrict__ frow = sf + c * NPTS;
            float v[4];
            #pragma unroll
            for (int j = 0; j < 4; j++) {
                int q = head[cl4 + j];
                float s = 0.f;
                while (q >= 0) { s += frow[q]; q = nxt[q]; }
                v[j] = s;
            }
            *reinterpret_cast<float4*>(ob + c * NCELLS) =
                make_float4(v[0], v[1], v[2], v[3]);
        }
    }
}

extern "C" void kernel_launch(void* const* d_in, const int* in_sizes, int n_in,
                              void* d_out, int out_size)
{
    const float* features = (const float*)d_in[0];   // 64*128*16*16
    const float* depth    = (const float*)d_in[1];   // 64*1*16*16
    const float* cam      = (const float*)d_in[2];   // 3*256
    float*       out      = (float*)d_out;           // 64*128*32*32

    dim3 grid(GROUPS, NBATCH);
    voxelize_kernel<<<grid, 256>>>(features, depth, cam, out);
}